// round 10
// baseline (speedup 1.0000x reference)
#include <cuda_runtime.h>
#include <cstddef>

#define NCOL 2048
#define NROW 16384
#define THREADS 128
#define WPB 4                    // warps per block
#define RPW 14                   // rows per warp (lanes 14..31 idle in compute)
#define RPB (WPB * RPW)          // 56 rows per block
#define W 64                     // tile width (columns)
#define NT (NCOL / W)            // 32 tiles
#define BT 4                     // tiles per batch (1KB per row per batch)
#define NB (NT / BT)             // 8 batches
#define LDW 68                   // padded smem row stride (272B = 17*16, float4-safe)
#define TILE_F (RPW * LDW)       // 952 floats per tile buffer
#define NINB 8                   // input ring: 2 batches of 4 tiles
#define NOUTB 6                  // output staging ring (ranges mod 6)
#define WBUF_F ((NINB + NOUTB) * TILE_F)
#define SMEM_BYTES ((2 * NCOL + WPB * WBUF_F) * 4)   // 229,632B -> 1 CTA/SM
#define CHUNKS ((RPW * (W / 4)) / 32)   // 7 float4-chunks per lane per tile

__device__ __forceinline__ void cp_async16(float* smem_dst, const float* gsrc) {
    unsigned s = (unsigned)__cvta_generic_to_shared(smem_dst);
    asm volatile("cp.async.cg.shared.global [%0], [%1], 16;" :: "r"(s), "l"(gsrc));
}
__device__ __forceinline__ void cp_commit() { asm volatile("cp.async.commit_group;"); }

__global__ void __launch_bounds__(THREADS, 1)
ring_givens_kernel(const float* __restrict__ x,
                   const float* __restrict__ angles,
                   float* __restrict__ out) {
    extern __shared__ float smem[];
    float2* cs = (float2*)smem;                       // [2048] (cos, sin)
    const int tid  = threadIdx.x;
    const int wid  = tid >> 5;
    const int lane = tid & 31;

    float* inb = smem + 2 * NCOL + wid * WBUF_F;      // 8 input tile buffers
    float* otb = inb + NINB * TILE_F;                 // 6 staging tile buffers

    const long long base = ((long long)blockIdx.x * WPB + wid) * RPW;
    const bool active = (base < NROW);

    // --- prologue: prefetch batches 7 and 6; page-friendly order:
    //     per row-pair, the 4 tiles' 256B chunks issued consecutively ascending
    if (active) {
        #pragma unroll
        for (int p = 0; p < 2; ++p) {
            int tb = BT * (NB - 1 - p);               // 28 then 24
            #pragma unroll
            for (int j = 0; j < CHUNKS; ++j) {
                #pragma unroll
                for (int b = 0; b < BT; ++b) {
                    int it = tb + b;
                    int q = lane + 32 * j, r = q >> 4, c4 = (q & 15) << 2;
                    long long grow = base + r;
                    if (grow >= NROW) grow = NROW - 1;   // clamp (tail warps)
                    cp_async16(inb + (it & 7) * TILE_F + r * LDW + c4,
                               x + grow * (long long)NCOL + it * W + c4);
                }
            }
            cp_commit();
        }
    }

    // --- cos/sin table (block-cooperative, overlaps prefetch) ---
    for (int k = tid; k < NCOL; k += THREADS) {
        float sv, cv;
        sincosf(angles[k], &sv, &cv);
        cs[k] = make_float2(cv, sv);
    }
    __syncthreads();          // only block barrier
    if (!active) return;

    const bool wr = (lane < RPW) && (base + lane < NROW);  // lane owns a row
    const int  cl = wr ? lane : 0;
    const float x0 = wr ? x[(base + cl) * (long long)NCOL] : 0.f;  // wrap partner

    const float4* csf4 = (const float4*)cs;  // {c(2m), s(2m), c(2m+1), s(2m+1)}

    float t = 0.f, v0run = 0.f;
    float c0r = 0.f, c1r = 0.f, c2r = 0.f;   // carried outputs

    for (int m = NB - 1; m >= 0; --m) {
        // batch m's group was committed 2 iterations ago; only 1 newer group
        asm volatile("cp.async.wait_group 1;");
        __syncwarp();

        // ---- compute 4 tiles, descending (i = 4m+3 .. 4m) ----
        if (wr) {
            #pragma unroll
            for (int tt = BT - 1; tt >= 0; --tt) {
                const int i  = BT * m + tt;
                const int k0 = i * W;
                const float* bin = inb + (i & 7) * TILE_F + cl * LDW;
                float* otc = otb + (i % 6) * TILE_F + cl * LDW;       // range i
                float* otn = otb + ((i + 1) % 6) * TILE_F + cl * LDW; // range i+1

                #pragma unroll
                for (int q = 15; q >= 0; --q) {
                    float4 u4 = *(const float4*)(bin + 4 * q);
                    float4 cB = csf4[(k0 >> 1) + 2 * q];      // k0+4q, k0+4q+1
                    float4 cA = csf4[(k0 >> 1) + 2 * q + 1];  // k0+4q+2, +3

                    if (i == NT - 1 && q == 15) {
                        // wrap rotation k = 2047: plane (2047, 0)
                        t     = cA.z * u4.w - cA.w * x0;
                        v0run = cA.w * u4.w + cA.z * x0;
                    } else {
                        float su3 = cA.w * u4.w, cu3 = cA.z * u4.w;
                        float O3  = fmaf(cA.z, t, su3);       // out[k0+4q+4]
                        t         = fmaf(-cA.w, t, cu3);
                        float4 st4 = make_float4(O3, c0r, c1r, c2r);
                        if (q == 15) *(float4*)otn = st4;               // slots 0..3
                        else         *(float4*)(otc + 4 * q + 4) = st4; // 4q+4..+7
                    }
                    float su2 = cA.y * u4.z, cu2 = cA.x * u4.z;
                    float O2  = fmaf(cA.x, t, su2);
                    t         = fmaf(-cA.y, t, cu2);
                    float su1 = cB.w * u4.y, cu1 = cB.z * u4.y;
                    float O1  = fmaf(cB.z, t, su1);
                    t         = fmaf(-cB.w, t, cu1);
                    float u0  = (i == 0 && q == 0) ? v0run : u4.x;
                    float su0 = cB.y * u0, cu0 = cB.x * u0;
                    float O0  = fmaf(cB.x, t, su0);
                    t         = fmaf(-cB.y, t, cu0);
                    c0r = O0; c1r = O1; c2r = O2;
                }
            }
        }
        __syncwarp();     // compute done: input slots free, staging visible

        // ---- prefetch batch m-2 into freed slots (page-friendly order) ----
        if (m >= 2) {
            int tb = BT * (m - 2);
            #pragma unroll
            for (int j = 0; j < CHUNKS; ++j) {
                #pragma unroll
                for (int b = 0; b < BT; ++b) {
                    int it = tb + b;
                    int q = lane + 32 * j, r = q >> 4, c4 = (q & 15) << 2;
                    long long grow = base + r;
                    if (grow >= NROW) grow = NROW - 1;
                    cp_async16(inb + (it & 7) * TILE_F + r * LDW + c4,
                               x + grow * (long long)NCOL + it * W + c4);
                }
            }
        }
        cp_commit();      // unconditional: uniform group accounting

        // ---- store completed ranges 4m+1..4m+4: 1KB/row contiguous bursts ----
        #pragma unroll
        for (int j = 0; j < CHUNKS; ++j) {
            #pragma unroll
            for (int rg = 0; rg < BT; ++rg) {
                int rr = BT * m + 1 + rg;
                if (rr < NT) {
                    const float* sb = otb + (rr % 6) * TILE_F;
                    int q = lane + 32 * j, r = q >> 4, c4 = (q & 15) << 2;
                    long long grow = base + r;
                    if (grow < NROW)
                        *(float4*)(out + grow * (long long)NCOL + rr * W + c4) =
                            *(const float4*)(sb + r * LDW + c4);
                }
            }
        }
    }

    // finalize range 0 (slot 0): quad0 = {out[0]=t, carries from tile0 q=0}
    if (wr) *(float4*)(otb + cl * LDW) = make_float4(t, c0r, c1r, c2r);
    __syncwarp();
    #pragma unroll
    for (int j = 0; j < CHUNKS; ++j) {
        int q = lane + 32 * j, r = q >> 4, c4 = (q & 15) << 2;
        long long grow = base + r;
        if (grow < NROW)
            *(float4*)(out + grow * (long long)NCOL + c4) =
                *(const float4*)(otb + r * LDW + c4);
    }
}

extern "C" void kernel_launch(void* const* d_in, const int* in_sizes, int n_in,
                              void* d_out, int out_size) {
    const float* x      = (const float*)d_in[0];
    const float* angles = (const float*)d_in[1];
    if (n_in >= 2 && in_sizes[0] < in_sizes[1]) {   // defensive ordering
        x      = (const float*)d_in[1];
        angles = (const float*)d_in[0];
    }
    float* out = (float*)d_out;

    cudaFuncSetAttribute(ring_givens_kernel,
                         cudaFuncAttributeMaxDynamicSharedMemorySize, SMEM_BYTES);
    int grid = (NROW + RPB - 1) / RPB;   // 293
    ring_givens_kernel<<<grid, THREADS, SMEM_BYTES>>>(x, angles, out);
}

// round 11
// speedup vs baseline: 1.0352x; 1.0352x over previous
#include <cuda_runtime.h>
#include <cstddef>

#define NCOL 2048
#define NROW 16384
#define THREADS 128
#define WPB 4                    // warps per block
#define RPW 14                   // rows per warp (lanes 14..31 idle in compute)
#define RPB (WPB * RPW)          // 56 rows per block
#define W 64                     // tile width (columns)
#define NT (NCOL / W)            // 32 tiles
#define BT 2                     // tiles per batch -> 512B per row per batch
#define NB (NT / BT)             // 16 batches
#define LDW 68                   // padded smem row stride (272B = 17*16, float4-safe)
#define TILE_F (RPW * LDW)       // 952 floats per tile buffer
#define NINB 6                   // input ring: 3 batches of 2 tiles
#define NOUTB 3                  // output staging ring (ranges mod 3)
#define WBUF_F ((NINB + NOUTB) * TILE_F)
#define SMEM_BYTES ((2 * NCOL + WPB * WBUF_F) * 4)   // 153,472B -> 1 CTA/SM
#define CHUNKS ((RPW * (W / 4)) / 32)   // 7 float4-chunks per lane per tile

__device__ __forceinline__ void cp_async16(float* smem_dst, const float* gsrc) {
    unsigned s = (unsigned)__cvta_generic_to_shared(smem_dst);
    asm volatile("cp.async.cg.shared.global [%0], [%1], 16;" :: "r"(s), "l"(gsrc));
}
__device__ __forceinline__ void cp_commit() { asm volatile("cp.async.commit_group;"); }

__global__ void __launch_bounds__(THREADS, 1)
ring_givens_kernel(const float* __restrict__ x,
                   const float* __restrict__ angles,
                   float* __restrict__ out) {
    extern __shared__ float smem[];
    float2* cs = (float2*)smem;                       // [2048] (cos, sin)
    const int tid  = threadIdx.x;
    const int wid  = tid >> 5;
    const int lane = tid & 31;

    float* inb = smem + 2 * NCOL + wid * WBUF_F;      // 6 input tile buffers
    float* otb = inb + NINB * TILE_F;                 // 3 staging tile buffers

    const long long base = ((long long)blockIdx.x * WPB + wid) * RPW;
    const bool active = (base < NROW);

    // --- prologue: prefetch batches 15,14,13 (tiles 31..26), one group each;
    //     row-major within a batch -> 512B ascending bursts per row
    if (active) {
        #pragma unroll
        for (int p = 0; p < 3; ++p) {
            int tb = BT * (NB - 1 - p);
            #pragma unroll
            for (int j = 0; j < CHUNKS; ++j) {
                #pragma unroll
                for (int b = 0; b < BT; ++b) {
                    int it = tb + b;
                    int q = lane + 32 * j, r = q >> 4, c4 = (q & 15) << 2;
                    long long grow = base + r;
                    if (grow >= NROW) grow = NROW - 1;   // clamp (tail warps)
                    cp_async16(inb + (it % NINB) * TILE_F + r * LDW + c4,
                               x + grow * (long long)NCOL + it * W + c4);
                }
            }
            cp_commit();
        }
    }

    // --- cos/sin table (block-cooperative, overlaps prefetch) ---
    for (int k = tid; k < NCOL; k += THREADS) {
        float sv, cv;
        sincosf(angles[k], &sv, &cv);
        cs[k] = make_float2(cv, sv);
    }
    __syncthreads();          // only block barrier
    if (!active) return;

    const bool wr = (lane < RPW) && (base + lane < NROW);  // lane owns a row
    const int  cl = wr ? lane : 0;
    const float x0 = wr ? x[(base + cl) * (long long)NCOL] : 0.f;  // wrap partner

    const float4* csf4 = (const float4*)cs;  // {c(2m), s(2m), c(2m+1), s(2m+1)}

    float t = 0.f, v0run = 0.f;
    float c0r = 0.f, c1r = 0.f, c2r = 0.f;   // carried outputs

    for (int m = NB - 1; m >= 0; --m) {
        // keep <=2 newer groups outstanding -> batch m has landed,
        // batches m-1, m-2 still in flight (3-batch depth preserved)
        asm volatile("cp.async.wait_group 2;");
        __syncwarp();

        // ---- compute tiles 2m+1 then 2m (descending) ----
        if (wr) {
            #pragma unroll
            for (int tt = BT - 1; tt >= 0; --tt) {
                const int i  = BT * m + tt;
                const int k0 = i * W;
                const float* bin = inb + (i % NINB) * TILE_F + cl * LDW;
                float* otc = otb + (i % NOUTB) * TILE_F + cl * LDW;       // range i
                float* otn = otb + ((i + 1) % NOUTB) * TILE_F + cl * LDW; // range i+1

                #pragma unroll
                for (int q = 15; q >= 0; --q) {
                    float4 u4 = *(const float4*)(bin + 4 * q);
                    float4 cB = csf4[(k0 >> 1) + 2 * q];      // k0+4q, k0+4q+1
                    float4 cA = csf4[(k0 >> 1) + 2 * q + 1];  // k0+4q+2, +3

                    if (i == NT - 1 && q == 15) {
                        // wrap rotation k = 2047: plane (2047, 0)
                        t     = cA.z * u4.w - cA.w * x0;
                        v0run = cA.w * u4.w + cA.z * x0;
                    } else {
                        float su3 = cA.w * u4.w, cu3 = cA.z * u4.w;
                        float O3  = fmaf(cA.z, t, su3);       // out[k0+4q+4]
                        t         = fmaf(-cA.w, t, cu3);
                        float4 st4 = make_float4(O3, c0r, c1r, c2r);
                        if (q == 15) *(float4*)otn = st4;               // slots 0..3
                        else         *(float4*)(otc + 4 * q + 4) = st4; // 4q+4..+7
                    }
                    float su2 = cA.y * u4.z, cu2 = cA.x * u4.z;
                    float O2  = fmaf(cA.x, t, su2);
                    t         = fmaf(-cA.y, t, cu2);
                    float su1 = cB.w * u4.y, cu1 = cB.z * u4.y;
                    float O1  = fmaf(cB.z, t, su1);
                    t         = fmaf(-cB.w, t, cu1);
                    float u0  = (i == 0 && q == 0) ? v0run : u4.x;
                    float su0 = cB.y * u0, cu0 = cB.x * u0;
                    float O0  = fmaf(cB.x, t, su0);
                    t         = fmaf(-cB.y, t, cu0);
                    c0r = O0; c1r = O1; c2r = O2;
                }
            }
        }
        __syncwarp();     // input slots 2m,2m+1 free; staging writes visible

        // ---- prefetch batch m-3 into freed slots (row-major, 512B bursts) ----
        if (m >= 3) {
            int tb = BT * (m - 3);
            #pragma unroll
            for (int j = 0; j < CHUNKS; ++j) {
                #pragma unroll
                for (int b = 0; b < BT; ++b) {
                    int it = tb + b;
                    int q = lane + 32 * j, r = q >> 4, c4 = (q & 15) << 2;
                    long long grow = base + r;
                    if (grow >= NROW) grow = NROW - 1;
                    cp_async16(inb + (it % NINB) * TILE_F + r * LDW + c4,
                               x + grow * (long long)NCOL + it * W + c4);
                }
            }
        }
        cp_commit();      // unconditional: uniform group accounting

        // ---- store completed ranges 2m+1, 2m+2: 512B/row paired bursts ----
        #pragma unroll
        for (int j = 0; j < CHUNKS; ++j) {
            #pragma unroll
            for (int rg = 0; rg < BT; ++rg) {
                int rr = BT * m + 1 + rg;
                if (rr < NT) {
                    const float* sb = otb + (rr % NOUTB) * TILE_F;
                    int q = lane + 32 * j, r = q >> 4, c4 = (q & 15) << 2;
                    long long grow = base + r;
                    if (grow < NROW)
                        *(float4*)(out + grow * (long long)NCOL + rr * W + c4) =
                            *(const float4*)(sb + r * LDW + c4);
                }
            }
        }
    }

    // finalize range 0 (buffer 0): quad0 = {out[0]=t, carries from tile0 q=0}
    if (wr) *(float4*)(otb + cl * LDW) = make_float4(t, c0r, c1r, c2r);
    __syncwarp();
    #pragma unroll
    for (int j = 0; j < CHUNKS; ++j) {
        int q = lane + 32 * j, r = q >> 4, c4 = (q & 15) << 2;
        long long grow = base + r;
        if (grow < NROW)
            *(float4*)(out + grow * (long long)NCOL + c4) =
                *(const float4*)(otb + r * LDW + c4);
    }
}

extern "C" void kernel_launch(void* const* d_in, const int* in_sizes, int n_in,
                              void* d_out, int out_size) {
    const float* x      = (const float*)d_in[0];
    const float* angles = (const float*)d_in[1];
    if (n_in >= 2 && in_sizes[0] < in_sizes[1]) {   // defensive ordering
        x      = (const float*)d_in[1];
        angles = (const float*)d_in[0];
    }
    float* out = (float*)d_out;

    cudaFuncSetAttribute(ring_givens_kernel,
                         cudaFuncAttributeMaxDynamicSharedMemorySize, SMEM_BYTES);
    int grid = (NROW + RPB - 1) / RPB;   // 293
    ring_givens_kernel<<<grid, THREADS, SMEM_BYTES>>>(x, angles, out);
}

// round 12
// speedup vs baseline: 1.5860x; 1.5321x over previous
#include <cuda_runtime.h>
#include <cstddef>

#define NCOL 2048
#define NROW 16384
#define THREADS 128
#define WPB 4                    // warps per block
#define RPW 28                   // rows per warp (lanes 28..31 idle in compute)
#define RPB (WPB * RPW)          // 112 rows per block
#define W 64                     // tile width (columns)
#define NT (NCOL / W)            // 32 tiles
#define LDW 68                   // padded smem row stride (272B = 17*16, float4-safe)
#define TILE_F (RPW * LDW)       // 1904 floats per tile buffer
#define NIN 5                    // input ring depth (mod-5 -> early prefetch)
#define WBUF_F ((NIN + 2) * TILE_F)
#define SMEM_BYTES ((2 * NCOL + WPB * WBUF_F) * 4)   // 229,632B -> 1 CTA/SM
#define CHUNKS ((RPW * (W / 4)) / 32)   // 14 float4-chunks per lane per tile

__device__ __forceinline__ void cp_async16(float* smem_dst, const float* gsrc) {
    unsigned s = (unsigned)__cvta_generic_to_shared(smem_dst);
    asm volatile("cp.async.cg.shared.global [%0], [%1], 16;" :: "r"(s), "l"(gsrc));
}
__device__ __forceinline__ void cp_commit() { asm volatile("cp.async.commit_group;"); }

__global__ void __launch_bounds__(THREADS, 1)
ring_givens_kernel(const float* __restrict__ x,
                   const float* __restrict__ angles,
                   float* __restrict__ out) {
    extern __shared__ float smem[];
    float2* cs = (float2*)smem;                       // [2048] (cos, sin)
    const int tid  = threadIdx.x;
    const int wid  = tid >> 5;
    const int lane = tid & 31;

    float* inb = smem + 2 * NCOL + wid * WBUF_F;      // 5 input tile buffers
    float* otb = inb + NIN * TILE_F;                  // 2 output staging buffers

    const long long base = ((long long)blockIdx.x * WPB + wid) * RPW;
    const bool active = (base < NROW);

    // --- prologue: prefetch tiles 31..28 (4 groups) ---
    if (active) {
        #pragma unroll
        for (int p = 0; p < 4; ++p) {
            int it = NT - 1 - p;
            float* buf = inb + (it % NIN) * TILE_F;
            #pragma unroll
            for (int j = 0; j < CHUNKS; ++j) {
                int q = lane + 32 * j, r = q >> 4, c4 = (q & 15) << 2;
                long long grow = base + r;
                if (grow >= NROW) grow = NROW - 1;     // clamp (tail warps)
                cp_async16(buf + r * LDW + c4,
                           x + grow * (long long)NCOL + it * W + c4);
            }
            cp_commit();
        }
    }

    // --- cos/sin table (block-cooperative, overlaps prefetch) ---
    for (int k = tid; k < NCOL; k += THREADS) {
        float sv, cv;
        sincosf(angles[k], &sv, &cv);
        cs[k] = make_float2(cv, sv);
    }
    __syncthreads();          // only block barrier
    if (!active) return;

    const bool wr = (lane < RPW) && (base + lane < NROW);  // lane owns a row
    const int  cl = wr ? lane : 0;
    const float x0 = wr ? x[(base + cl) * (long long)NCOL] : 0.f;  // wrap partner

    const float4* csf4 = (const float4*)cs;  // {c(2m), s(2m), c(2m+1), s(2m+1)}

    float t = 0.f, v0run = 0.f;
    float c0r = 0.f, c1r = 0.f, c2r = 0.f;   // carried outputs

    for (int i = NT - 1; i >= 0; --i) {
        // tile i landed (3 newer groups may remain in flight)
        asm volatile("cp.async.wait_group 3;");
        __syncwarp();

        // ---- EARLY prefetch: tile i-4 -> slot (i-4)%5 (distinct from live
        //      slots i..i-3); loads stay in flight through the whole compute.
        //      Always commit so group accounting stays uniform in the tail.
        if (i >= 4) {
            int ip = i - 4;
            float* buf = inb + (ip % NIN) * TILE_F;
            #pragma unroll
            for (int j = 0; j < CHUNKS; ++j) {
                int q = lane + 32 * j, r = q >> 4, c4 = (q & 15) << 2;
                long long grow = base + r;
                if (grow >= NROW) grow = NROW - 1;
                cp_async16(buf + r * LDW + c4,
                           x + grow * (long long)NCOL + ip * W + c4);
            }
        }
        cp_commit();

        const int k0 = i * W;

        // ---- compute tile i ----
        if (wr) {
            const float* bin = inb + (i % NIN) * TILE_F + cl * LDW;
            float* otc = otb + (i & 1) * TILE_F + cl * LDW;        // [k0, k0+W)
            float* otn = otb + ((i + 1) & 1) * TILE_F + cl * LDW;  // [k0+W, ..)

            #pragma unroll
            for (int q = 15; q >= 0; --q) {
                float4 u4 = *(const float4*)(bin + 4 * q);
                float4 cB = csf4[(k0 >> 1) + 2 * q];      // k0+4q, k0+4q+1
                float4 cA = csf4[(k0 >> 1) + 2 * q + 1];  // k0+4q+2, +3

                if (i == NT - 1 && q == 15) {
                    // wrap rotation k = 2047: plane (2047, 0). No output yet.
                    t     = cA.z * u4.w - cA.w * x0;
                    v0run = cA.w * u4.w + cA.z * x0;
                } else {
                    float su3 = cA.w * u4.w, cu3 = cA.z * u4.w;
                    float O3  = fmaf(cA.z, t, su3);       // out[k0+4q+4]
                    t         = fmaf(-cA.w, t, cu3);
                    float4 st4 = make_float4(O3, c0r, c1r, c2r);
                    if (q == 15) *(float4*)otn = st4;                // slots 0..3
                    else         *(float4*)(otc + 4 * q + 4) = st4;  // 4q+4..+7
                }
                float su2 = cA.y * u4.z, cu2 = cA.x * u4.z;
                float O2  = fmaf(cA.x, t, su2);
                t         = fmaf(-cA.y, t, cu2);
                float su1 = cB.w * u4.y, cu1 = cB.z * u4.y;
                float O1  = fmaf(cB.z, t, su1);
                t         = fmaf(-cB.w, t, cu1);
                float u0  = (i == 0 && q == 0) ? v0run : u4.x;
                float su0 = cB.y * u0, cu0 = cB.x * u0;
                float O0  = fmaf(cB.x, t, su0);
                t         = fmaf(-cB.y, t, cu0);
                c0r = O0; c1r = O1; c2r = O2;
            }
        }

        // Load-bearing: orders tile-i reads before iteration i-1's prefetch
        // into slot i%5, and makes staging writes visible to all lanes.
        __syncwarp();

        // ---- store the completed buffer: out columns [(i+1)*W, (i+2)*W) ----
        if (i < NT - 1) {
            const float* sb = otb + ((i + 1) & 1) * TILE_F;
            const int col0 = (i + 1) * W;
            #pragma unroll
            for (int j = 0; j < CHUNKS; ++j) {
                int q = lane + 32 * j, r = q >> 4, c4 = (q & 15) << 2;
                long long grow = base + r;
                if (grow < NROW)
                    *(float4*)(out + grow * (long long)NCOL + col0 + c4) =
                        *(const float4*)(sb + r * LDW + c4);
            }
        }
    }

    // finalize buffer parity 0 (out cols [0, W)): slot0 = {out[0]=t, carries}
    if (wr) *(float4*)(otb + cl * LDW) = make_float4(t, c0r, c1r, c2r);
    __syncwarp();
    #pragma unroll
    for (int j = 0; j < CHUNKS; ++j) {
        int q = lane + 32 * j, r = q >> 4, c4 = (q & 15) << 2;
        long long grow = base + r;
        if (grow < NROW)
            *(float4*)(out + grow * (long long)NCOL + c4) =
                *(const float4*)(otb + r * LDW + c4);
    }
}

extern "C" void kernel_launch(void* const* d_in, const int* in_sizes, int n_in,
                              void* d_out, int out_size) {
    const float* x      = (const float*)d_in[0];
    const float* angles = (const float*)d_in[1];
    if (n_in >= 2 && in_sizes[0] < in_sizes[1]) {   // defensive ordering
        x      = (const float*)d_in[1];
        angles = (const float*)d_in[0];
    }
    float* out = (float*)d_out;

    cudaFuncSetAttribute(ring_givens_kernel,
                         cudaFuncAttributeMaxDynamicSharedMemorySize, SMEM_BYTES);
    int grid = (NROW + RPB - 1) / RPB;   // 147
    ring_givens_kernel<<<grid, THREADS, SMEM_BYTES>>>(x, angles, out);
}